// round 5
// baseline (speedup 1.0000x reference)
#include <cuda_runtime.h>
#include <cstdint>

// Problem constants
#define BB   16
#define CIN  8
#define COUT 32
#define HH   64
#define WW   64
#define K2   9
#define NC   8          // spline coefficients per feature
#define NF   9          // features per cin: silu + 8 spline bases
#define THW  16         // tile width
#define THH  8          // tile height
#define CTHREADS 128

#define FR   (THH + 2)                 // 10 halo rows
#define FC   (THW + 2)                 // 18 halo cols
#define FPIX (FR * FC)                 // 180
#define SF_FLOATS (NF * FPIX)          // 1620
#define WCHUNK   (NF * K2 * COUT)      // 2592 floats per cin

// Fused weights, computed once per launch by kan_fuse_kernel.
// Layout: gw[c][f][tap][oc], oc fastest.
__device__ float g_fused[CIN * WCHUNK];

__device__ __forceinline__ float silu_f(float x) {
    return x / (1.0f + __expf(-x));
}

// Packed f32x2 FMA: one issue slot, two fp32 FMAs, bit-identical rounding.
__device__ __forceinline__ void ffma2(unsigned long long& d,
                                      unsigned long long a,
                                      unsigned long long b) {
    asm("fma.rn.f32x2 %0, %1, %2, %0;" : "+l"(d) : "l"(a), "l"(b));
}

__device__ __forceinline__ unsigned long long pack2(float v) {
    unsigned long long p;
    asm("mov.b64 %0, {%1, %1};" : "=l"(p) : "f"(v));
    return p;
}

__device__ __forceinline__ void unpack2(unsigned long long p, float& lo, float& hi) {
    asm("mov.b64 {%0, %1}, %2;" : "=f"(lo), "=f"(hi) : "l"(p));
}

__device__ __forceinline__ void cp_async16(uint32_t saddr, const void* gptr) {
    asm volatile("cp.async.cg.shared.global [%0], [%1], 16;"
                 :: "r"(saddr), "l"(gptr));
}

// De Boor-Cox recursion, degree 3, uniform knots t[j] = (j-3)*0.4 - 1.0.
// Matches the reference recursion exactly (same formula, fp32).
__device__ __forceinline__ void bspline8(float x, float* __restrict__ out) {
    float t[12];
    #pragma unroll
    for (int j = 0; j < 12; ++j) t[j] = (float)(j - 3) * 0.4f - 1.0f;

    float b[11];
    #pragma unroll
    for (int j = 0; j < 11; ++j)
        b[j] = (x >= t[j] && x < t[j + 1]) ? 1.0f : 0.0f;

    #pragma unroll
    for (int k = 1; k <= 3; ++k) {
        #pragma unroll
        for (int j = 0; j < 10; ++j) {
            if (j < 11 - k) {
                b[j] = (x - t[j]) / (t[j + k] - t[j]) * b[j]
                     + (t[j + k + 1] - x) / (t[j + k + 1] - t[j + 1]) * b[j + 1];
            }
        }
    }
    #pragma unroll
    for (int s = 0; s < NC; ++s) out[s] = b[s];
}

// ---- Kernel A: fuse base/spline weights into g_fused ----
__global__ void kan_fuse_kernel(const float* __restrict__ base_w,
                                const float* __restrict__ spline_w,
                                const float* __restrict__ spline_s)
{
    const int i = blockIdx.x * blockDim.x + threadIdx.x;
    if (i >= CIN * WCHUNK) return;
    const int oc  = i & (COUT - 1);
    const int tap = (i / COUT) % K2;
    const int f   = (i / (COUT * K2)) % NF;
    const int c   = i / WCHUNK;
    const int widx = (oc * CIN + c) * K2 + tap;
    float w;
    if (f == 0) w = base_w[widx];
    else        w = spline_w[widx * NC + (f - 1)] * spline_s[widx];
    g_fused[i] = w;
}

// ---- Kernel B: main conv ----
// Grid: 32 tiles (8 row-tiles x 4 col-tiles) x 16 batches = 512 CTAs, 128 thr.
// Thread: ocg = tid>>6 (16 oc each); pxp = tid&63: r2 = pxp>>4 (rows 2r2,
// 2r2+1), cc = pxp&15. Warp-uniform ocg -> weight LDS broadcast.
__global__ void __launch_bounds__(CTHREADS, 4)
kan_conv_kernel(const float* __restrict__ x,
                float* __restrict__ out)
{
    __shared__ float sF[SF_FLOATS];
    __shared__ float sW[2][WCHUNK];

    const int tid  = threadIdx.x;
    const int tile = blockIdx.x;      // 0..31
    const int b    = blockIdx.y;      // 0..15
    const int th0  = (tile >> 2) * THH;
    const int tw0  = (tile & 3) * THW;

    const int ocg = tid >> 6;         // 0..1
    const int pxp = tid & 63;
    const int r2  = pxp >> 4;         // 0..3
    const int cc  = pxp & 15;

    // halo pixel coords handled by this thread (i and i+128)
    const int pr0 = tid / FC,         pc0 = tid % FC;
    const int i1  = tid + CTHREADS;
    const int pr1 = i1 / FC,          pc1 = i1 % FC;
    const bool has1 = (i1 < FPIX);

    // ---- stage weights for c=0 (cp.async) + x prefetch for c=0 ----
    {
        const float4* src = reinterpret_cast<const float4*>(g_fused);
        for (int i = tid; i < WCHUNK / 4; i += CTHREADS)
            cp_async16((uint32_t)__cvta_generic_to_shared(&sW[0][i * 4]),
                       src + i);
        asm volatile("cp.async.commit_group;");
    }

    float xr0, xr1 = 0.0f;
    {
        const int gh0 = th0 + pr0 - 1, gw0 = tw0 + pc0 - 1;
        xr0 = (gh0 >= 0 && gh0 < HH && gw0 >= 0 && gw0 < WW)
                ? x[((b * CIN + 0) * HH + gh0) * WW + gw0] : 0.0f;
        if (has1) {
            const int gh1 = th0 + pr1 - 1, gw1 = tw0 + pc1 - 1;
            xr1 = (gh1 >= 0 && gh1 < HH && gw1 >= 0 && gw1 < WW)
                    ? x[((b * CIN + 0) * HH + gh1) * WW + gw1] : 0.0f;
        }
    }

    unsigned long long acc0[8], acc1[8];
    #pragma unroll
    for (int q = 0; q < 8; ++q) { acc0[q] = 0ULL; acc1[q] = 0ULL; }

    for (int c = 0; c < CIN; ++c) {
        const int buf = c & 1;

        // ---- feature gen for cin c (from prefetched regs) ----
        {
            float bs[NC];
            bspline8(xr0, bs);
            sF[tid] = silu_f(xr0);
            #pragma unroll
            for (int s = 0; s < NC; ++s) sF[(s + 1) * FPIX + tid] = bs[s];
            if (has1) {
                bspline8(xr1, bs);
                sF[i1] = silu_f(xr1);
                #pragma unroll
                for (int s = 0; s < NC; ++s) sF[(s + 1) * FPIX + i1] = bs[s];
            }
        }

        // ---- prefetch next cin: weights via cp.async, x into regs ----
        if (c < CIN - 1) {
            const float4* src =
                reinterpret_cast<const float4*>(g_fused + (c + 1) * WCHUNK);
            for (int i = tid; i < WCHUNK / 4; i += CTHREADS)
                cp_async16((uint32_t)__cvta_generic_to_shared(
                               &sW[1 - buf][i * 4]), src + i);
            asm volatile("cp.async.commit_group;");

            const int gh0 = th0 + pr0 - 1, gw0 = tw0 + pc0 - 1;
            xr0 = (gh0 >= 0 && gh0 < HH && gw0 >= 0 && gw0 < WW)
                    ? x[((b * CIN + c + 1) * HH + gh0) * WW + gw0] : 0.0f;
            if (has1) {
                const int gh1 = th0 + pr1 - 1, gw1 = tw0 + pc1 - 1;
                xr1 = (gh1 >= 0 && gh1 < HH && gw1 >= 0 && gw1 < WW)
                        ? x[((b * CIN + c + 1) * HH + gh1) * WW + gw1] : 0.0f;
            }
            asm volatile("cp.async.wait_group 1;");   // chunk c arrived
        } else {
            asm volatile("cp.async.wait_group 0;");
        }
        __syncthreads();   // features + weights visible

        // ---- conv-accumulate 9 feature planes of cin c ----
        #pragma unroll
        for (int f = 0; f < NF; ++f) {
            float f12[4][3];
            #pragma unroll
            for (int dh = 0; dh < 4; ++dh)
                #pragma unroll
                for (int dw = 0; dw < 3; ++dw)
                    f12[dh][dw] = sF[f * FPIX + (2 * r2 + dh) * FC + (cc + dw)];

            const float* wbase = &sW[buf][(f * K2) * COUT + ocg * 16];

            #pragma unroll
            for (int dh = 0; dh < 3; ++dh) {
                #pragma unroll
                for (int dw = 0; dw < 3; ++dw) {
                    const int tap = dh * 3 + dw;
                    const unsigned long long fp0 = pack2(f12[dh][dw]);
                    const unsigned long long fp1 = pack2(f12[dh + 1][dw]);
                    const ulonglong2* wv = reinterpret_cast<const ulonglong2*>(
                        wbase + tap * COUT);
                    #pragma unroll
                    for (int q = 0; q < 2; ++q) {
                        const ulonglong2 wa = wv[q * 2 + 0];
                        const ulonglong2 wb = wv[q * 2 + 1];
                        ffma2(acc0[q * 4 + 0], fp0, wa.x);
                        ffma2(acc0[q * 4 + 1], fp0, wa.y);
                        ffma2(acc0[q * 4 + 2], fp0, wb.x);
                        ffma2(acc0[q * 4 + 3], fp0, wb.y);
                        ffma2(acc1[q * 4 + 0], fp1, wa.x);
                        ffma2(acc1[q * 4 + 1], fp1, wa.y);
                        ffma2(acc1[q * 4 + 2], fp1, wb.x);
                        ffma2(acc1[q * 4 + 3], fp1, wb.y);
                    }
                }
            }
        }
        __syncthreads();   // done reading sF before next featgen overwrites
    }

    // ---- write out: 2 rows x 16 oc per thread ----
    const int gh0 = th0 + 2 * r2;
    const int gw  = tw0 + cc;
    #pragma unroll
    for (int j = 0; j < 8; ++j) {
        const int oc = ocg * 16 + 2 * j;
        float lo, hi;
        unpack2(acc0[j], lo, hi);
        out[((b * COUT + oc + 0) * HH + gh0) * WW + gw] = lo;
        out[((b * COUT + oc + 1) * HH + gh0) * WW + gw] = hi;
        unpack2(acc1[j], lo, hi);
        out[((b * COUT + oc + 0) * HH + gh0 + 1) * WW + gw] = lo;
        out[((b * COUT + oc + 1) * HH + gh0 + 1) * WW + gw] = hi;
    }
}

extern "C" void kernel_launch(void* const* d_in, const int* in_sizes, int n_in,
                              void* d_out, int out_size) {
    const float* x   = (const float*)d_in[0];
    const float* bw  = (const float*)d_in[1];
    const float* sw  = (const float*)d_in[2];
    const float* ss  = (const float*)d_in[3];
    float* out       = (float*)d_out;

    kan_fuse_kernel<<<(CIN * WCHUNK + 255) / 256, 256>>>(bw, sw, ss);

    dim3 grid(32, BB);   // 32 spatial tiles x 16 batches = 512 CTAs
    kan_conv_kernel<<<grid, CTHREADS>>>(x, out);
}

// round 6
// speedup vs baseline: 1.1328x; 1.1328x over previous
#include <cuda_runtime.h>

// Problem constants
#define BB   16
#define CIN  8
#define COUT 32
#define HH   64
#define WW   64
#define K2   9
#define NC   8          // spline coefficients per feature
#define NF   9          // features per cin: silu + 8 spline bases
#define TILE 16
#define THREADS 256

#define FROWS 18                       // TILE + 2 halo
#define FPIX  (FROWS * FROWS)          // 324
#define SF_FLOATS (NF * FPIX)          // 2916  (one cin's 9 feature planes)
#define WCHUNK   (NF * K2 * COUT)      // 2592  (one cin's fused weights)
#define SMEM_BYTES ((SF_FLOATS + WCHUNK) * 4)   // 22032

// Fused weights, computed once per launch by kan_fuse_kernel.
// Layout: gw[c][f][tap][oc], c=cin, f=feature(0=silu,1..8=spline), oc fastest.
__device__ float g_fused[CIN * NF * K2 * COUT];

__device__ __forceinline__ float silu_f(float x) {
    return x / (1.0f + __expf(-x));
}

// Packed f32x2 FMA: one issue slot, two fp32 FMAs, bit-identical rounding.
__device__ __forceinline__ void ffma2(unsigned long long& d,
                                      unsigned long long a,
                                      unsigned long long b) {
    asm("fma.rn.f32x2 %0, %1, %2, %0;" : "+l"(d) : "l"(a), "l"(b));
}

__device__ __forceinline__ unsigned long long pack2(float v) {
    unsigned long long p;
    asm("mov.b64 %0, {%1, %1};" : "=l"(p) : "f"(v));
    return p;
}

__device__ __forceinline__ void unpack2(unsigned long long p, float& lo, float& hi) {
    asm("mov.b64 {%0, %1}, %2;" : "=f"(lo), "=f"(hi) : "l"(p));
}

// De Boor-Cox recursion, degree 3, uniform knots t[j] = (j-3)*0.4 - 1.0.
// Matches the reference recursion exactly (same formula, fp32).
__device__ __forceinline__ void bspline8(float x, float* __restrict__ out) {
    float t[12];
    #pragma unroll
    for (int j = 0; j < 12; ++j) t[j] = (float)(j - 3) * 0.4f - 1.0f;

    float b[11];
    #pragma unroll
    for (int j = 0; j < 11; ++j)
        b[j] = (x >= t[j] && x < t[j + 1]) ? 1.0f : 0.0f;

    #pragma unroll
    for (int k = 1; k <= 3; ++k) {
        #pragma unroll
        for (int j = 0; j < 10; ++j) {
            if (j < 11 - k) {
                b[j] = (x - t[j]) / (t[j + k] - t[j]) * b[j]
                     + (t[j + k + 1] - x) / (t[j + k + 1] - t[j + 1]) * b[j + 1];
            }
        }
    }
    #pragma unroll
    for (int s = 0; s < NC; ++s) out[s] = b[s];
}

// ---- Kernel A: fuse base/spline weights into g_fused ----
__global__ void kan_fuse_kernel(const float* __restrict__ base_w,
                                const float* __restrict__ spline_w,
                                const float* __restrict__ spline_s)
{
    const int i = blockIdx.x * blockDim.x + threadIdx.x;
    if (i >= CIN * NF * K2 * COUT) return;
    const int oc  = i & (COUT - 1);
    const int tap = (i / COUT) % K2;
    const int f   = (i / (COUT * K2)) % NF;
    const int c   = i / (COUT * K2 * NF);
    const int widx = (oc * CIN + c) * K2 + tap;
    float w;
    if (f == 0) w = base_w[widx];
    else        w = spline_w[widx * NC + (f - 1)] * spline_s[widx];
    g_fused[i] = w;
}

// ---- Kernel B: main conv.
// Thread layout: tid in [0,256): ocg = tid >> 7 (2 groups of 16 oc),
// pxp = tid & 127 -> vertical pixel pair: r2 = pxp >> 4 (rows 2*r2, 2*r2+1),
// cc = pxp & 15. Whole warp shares one ocg -> weight LDS are broadcasts.
__global__ void __launch_bounds__(THREADS, 3)
kan_conv_kernel(const float* __restrict__ x,
                float* __restrict__ out)
{
    extern __shared__ float smem[];
    float* sF = smem;                 // [NF][18][18]  (current cin)
    float* sW = smem + SF_FLOATS;     // [NF][9][COUT] (current cin)

    const int tid  = threadIdx.x;
    const int tile = blockIdx.x;      // 0..15
    const int b    = blockIdx.y;      // 0..15
    const int th0  = (tile >> 2) * TILE;
    const int tw0  = (tile & 3) * TILE;

    const int ocg = tid >> 7;         // 0..1
    const int pxp = tid & 127;
    const int r2  = pxp >> 4;         // 0..7  -> rows 2*r2, 2*r2+1
    const int cc  = pxp & 15;

    // Accumulators: 2 px x 16 oc = 32 floats as 16 packed f32x2.
    unsigned long long acc0[8], acc1[8];
    #pragma unroll
    for (int q = 0; q < 8; ++q) { acc0[q] = 0ULL; acc1[q] = 0ULL; }

    for (int c = 0; c < CIN; ++c) {
        __syncthreads();   // previous iteration done consuming sF/sW

        // Stage this cin's fused weight chunk (2592 floats) via float4.
        {
            const float4* src =
                reinterpret_cast<const float4*>(g_fused + c * WCHUNK);
            float4* dst = reinterpret_cast<float4*>(sW);
            for (int i = tid; i < WCHUNK / 4; i += THREADS)
                dst[i] = src[i];
        }

        // Feature planes for this cin: sF[f][18][18]
        for (int i = tid; i < FPIX; i += THREADS) {
            const int pc = i % FROWS;
            const int pr = i / FROWS;
            const int gh = th0 + pr - 1;
            const int gw = tw0 + pc - 1;
            float v = 0.0f;
            if (gh >= 0 && gh < HH && gw >= 0 && gw < WW)
                v = x[((b * CIN + c) * HH + gh) * WW + gw];
            float bs[NC];
            bspline8(v, bs);
            sF[i] = silu_f(v);
            #pragma unroll
            for (int s = 0; s < NC; ++s)
                sF[(s + 1) * FPIX + i] = bs[s];
        }
        __syncthreads();

        // Conv-accumulate 9 feature planes of this cin.
        // unroll 3 keeps the loop body small (I$-friendly) with enough ILP.
        #pragma unroll 3
        for (int f = 0; f < NF; ++f) {
            // 4 rows x 3 cols feature window for the vertical pixel pair.
            float f12[4][3];
            #pragma unroll
            for (int dh = 0; dh < 4; ++dh)
                #pragma unroll
                for (int dw = 0; dw < 3; ++dw)
                    f12[dh][dw] = sF[f * FPIX + (2 * r2 + dh) * FROWS + (cc + dw)];

            const float* wbase = sW + (f * K2) * COUT + ocg * 16;

            #pragma unroll
            for (int dh = 0; dh < 3; ++dh) {
                #pragma unroll
                for (int dw = 0; dw < 3; ++dw) {
                    const int tap = dh * 3 + dw;
                    const unsigned long long fp0 = pack2(f12[dh][dw]);
                    const unsigned long long fp1 = pack2(f12[dh + 1][dw]);
                    const ulonglong2* wv =
                        reinterpret_cast<const ulonglong2*>(wbase + tap * COUT);
                    #pragma unroll
                    for (int q = 0; q < 2; ++q) {
                        const ulonglong2 wa = wv[q * 2 + 0];
                        const ulonglong2 wb = wv[q * 2 + 1];
                        ffma2(acc0[q * 4 + 0], fp0, wa.x);
                        ffma2(acc0[q * 4 + 1], fp0, wa.y);
                        ffma2(acc0[q * 4 + 2], fp0, wb.x);
                        ffma2(acc0[q * 4 + 3], fp0, wb.y);
                        ffma2(acc1[q * 4 + 0], fp1, wa.x);
                        ffma2(acc1[q * 4 + 1], fp1, wa.y);
                        ffma2(acc1[q * 4 + 2], fp1, wb.x);
                        ffma2(acc1[q * 4 + 3], fp1, wb.y);
                    }
                }
            }
        }
    }

    // ---- Write out: 2 rows x 16 oc per thread ----
    const int gh0 = th0 + 2 * r2;
    const int gw  = tw0 + cc;
    #pragma unroll
    for (int j = 0; j < 8; ++j) {
        const int oc = ocg * 16 + 2 * j;
        float lo, hi;
        unpack2(acc0[j], lo, hi);
        out[((b * COUT + oc + 0) * HH + gh0) * WW + gw] = lo;
        out[((b * COUT + oc + 1) * HH + gh0) * WW + gw] = hi;
        unpack2(acc1[j], lo, hi);
        out[((b * COUT + oc + 0) * HH + gh0 + 1) * WW + gw] = lo;
        out[((b * COUT + oc + 1) * HH + gh0 + 1) * WW + gw] = hi;
    }
}

extern "C" void kernel_launch(void* const* d_in, const int* in_sizes, int n_in,
                              void* d_out, int out_size) {
    const float* x   = (const float*)d_in[0];
    const float* bw  = (const float*)d_in[1];
    const float* sw  = (const float*)d_in[2];
    const float* ss  = (const float*)d_in[3];
    float* out       = (float*)d_out;

    kan_fuse_kernel<<<(CIN * NF * K2 * COUT + 255) / 256, 256>>>(bw, sw, ss);

    cudaFuncSetAttribute(kan_conv_kernel,
                         cudaFuncAttributeMaxDynamicSharedMemorySize,
                         SMEM_BYTES);

    dim3 grid(16, BB);   // 16 spatial tiles x 16 batches
    kan_conv_kernel<<<grid, THREADS, SMEM_BYTES>>>(x, out);
}

// round 7
// speedup vs baseline: 1.2580x; 1.1105x over previous
#include <cuda_runtime.h>

// Problem constants
#define BB   16
#define CIN  8
#define COUT 32
#define HH   64
#define WW   64
#define K2   9
#define NC   8          // spline coefficients per feature
#define NF   9          // features per cin: silu + 8 spline bases
#define TILE 16
#define THREADS 512

#define FROWS 18                       // TILE + 2 halo
#define FPIX  (FROWS * FROWS)          // 324
#define SF_FLOATS (NF * FPIX)          // 2916  (one cin's 9 feature planes)
#define WCHUNK   (NF * K2 * COUT)      // 2592  (one cin's fused weights)

// Fused weights, computed once per launch by kan_fuse_kernel.
// Layout: gw[c][f][tap][oc], oc fastest.
__device__ float g_fused[CIN * WCHUNK];

__device__ __forceinline__ float silu_f(float x) {
    return x / (1.0f + __expf(-x));
}

// Packed f32x2 FMA: one issue slot, two fp32 FMAs, bit-identical rounding.
__device__ __forceinline__ void ffma2(unsigned long long& d,
                                      unsigned long long a,
                                      unsigned long long b) {
    asm("fma.rn.f32x2 %0, %1, %2, %0;" : "+l"(d) : "l"(a), "l"(b));
}

__device__ __forceinline__ unsigned long long pack2(float v) {
    unsigned long long p;
    asm("mov.b64 %0, {%1, %1};" : "=l"(p) : "f"(v));
    return p;
}

__device__ __forceinline__ void unpack2(unsigned long long p, float& lo, float& hi) {
    asm("mov.b64 {%0, %1}, %2;" : "=f"(lo), "=f"(hi) : "l"(p));
}

// De Boor-Cox recursion, degree 3, uniform knots t[j] = (j-3)*0.4 - 1.0.
// Matches the reference recursion exactly (same formula, fp32).
__device__ __forceinline__ void bspline8(float x, float* __restrict__ out) {
    float t[12];
    #pragma unroll
    for (int j = 0; j < 12; ++j) t[j] = (float)(j - 3) * 0.4f - 1.0f;

    float b[11];
    #pragma unroll
    for (int j = 0; j < 11; ++j)
        b[j] = (x >= t[j] && x < t[j + 1]) ? 1.0f : 0.0f;

    #pragma unroll
    for (int k = 1; k <= 3; ++k) {
        #pragma unroll
        for (int j = 0; j < 10; ++j) {
            if (j < 11 - k) {
                b[j] = (x - t[j]) / (t[j + k] - t[j]) * b[j]
                     + (t[j + k + 1] - x) / (t[j + k + 1] - t[j + 1]) * b[j + 1];
            }
        }
    }
    #pragma unroll
    for (int s = 0; s < NC; ++s) out[s] = b[s];
}

// ---- Kernel A: fuse base/spline weights into g_fused ----
__global__ void kan_fuse_kernel(const float* __restrict__ base_w,
                                const float* __restrict__ spline_w,
                                const float* __restrict__ spline_s)
{
    const int i = blockIdx.x * blockDim.x + threadIdx.x;
    if (i >= CIN * WCHUNK) return;
    const int oc  = i & (COUT - 1);
    const int tap = (i / COUT) % K2;
    const int f   = (i / (COUT * K2)) % NF;
    const int c   = i / WCHUNK;
    const int widx = (oc * CIN + c) * K2 + tap;
    float w;
    if (f == 0) w = base_w[widx];
    else        w = spline_w[widx * NC + (f - 1)] * spline_s[widx];
    g_fused[i] = w;
}

// ---- Kernel B: main conv.
// 512 threads: ocg = tid >> 7 (4 groups of 8 oc); pxp = tid & 127 ->
// vertical pixel pair r2 = pxp >> 4 (rows 2r2, 2r2+1), cc = pxp & 15.
// Warp-uniform ocg -> all weight LDS are broadcasts.
// Double-buffered features/weights: ONE barrier per cin; featgen(c+1)
// overlaps conv(c) across warps.
__global__ void __launch_bounds__(THREADS, 2)
kan_conv_kernel(const float* __restrict__ x,
                float* __restrict__ out)
{
    __shared__ float sF[2][SF_FLOATS];
    __shared__ float sW[2][WCHUNK];

    const int tid  = threadIdx.x;
    const int tile = blockIdx.x;      // 0..15
    const int b    = blockIdx.y;      // 0..15
    const int th0  = (tile >> 2) * TILE;
    const int tw0  = (tile & 3) * TILE;

    const int ocg = tid >> 7;         // 0..3
    const int pxp = tid & 127;
    const int r2  = pxp >> 4;         // 0..7
    const int cc  = pxp & 15;

    // ---- helpers as lambdas (inlined) ----
    auto stage_weights = [&](int c, float* dst) {
        const float4* src = reinterpret_cast<const float4*>(g_fused + c * WCHUNK);
        float4* d4 = reinterpret_cast<float4*>(dst);
        #pragma unroll
        for (int k = 0; k < 2; ++k) {
            const int i = tid + k * THREADS;
            if (i < WCHUNK / 4) d4[i] = src[i];
        }
    };
    auto featgen = [&](int c, float* dst) {
        if (tid < FPIX) {
            const int pc = tid % FROWS;
            const int pr = tid / FROWS;
            const int gh = th0 + pr - 1;
            const int gw = tw0 + pc - 1;
            float v = 0.0f;
            if (gh >= 0 && gh < HH && gw >= 0 && gw < WW)
                v = x[((b * CIN + c) * HH + gh) * WW + gw];
            float bs[NC];
            bspline8(v, bs);
            dst[tid] = silu_f(v);
            #pragma unroll
            for (int s = 0; s < NC; ++s)
                dst[(s + 1) * FPIX + tid] = bs[s];
        }
    };

    // Accumulators: 2 px x 8 oc = 16 floats as 8 packed f32x2.
    unsigned long long acc0[4], acc1[4];
    #pragma unroll
    for (int q = 0; q < 4; ++q) { acc0[q] = 0ULL; acc1[q] = 0ULL; }

    // ---- prologue: cin 0 into buffer 0 ----
    stage_weights(0, sW[0]);
    featgen(0, sF[0]);

    for (int c = 0; c < CIN; ++c) {
        const int buf = c & 1;
        __syncthreads();   // buf(c) ready; conv(c-1) done reading buf^1

        if (c < CIN - 1) {
            stage_weights(c + 1, sW[1 - buf]);
            featgen(c + 1, sF[1 - buf]);
        }

        // ---- conv-accumulate 9 feature planes of cin c ----
        const float* __restrict__ sFb = sF[buf];
        const float* __restrict__ sWb = sW[buf];
        #pragma unroll 3
        for (int f = 0; f < NF; ++f) {
            float f12[4][3];
            #pragma unroll
            for (int dh = 0; dh < 4; ++dh)
                #pragma unroll
                for (int dw = 0; dw < 3; ++dw)
                    f12[dh][dw] = sFb[f * FPIX + (2 * r2 + dh) * FROWS + (cc + dw)];

            const float* wbase = sWb + (f * K2) * COUT + ocg * 8;

            #pragma unroll
            for (int dh = 0; dh < 3; ++dh) {
                #pragma unroll
                for (int dw = 0; dw < 3; ++dw) {
                    const int tap = dh * 3 + dw;
                    const unsigned long long fp0 = pack2(f12[dh][dw]);
                    const unsigned long long fp1 = pack2(f12[dh + 1][dw]);
                    const ulonglong2* wv =
                        reinterpret_cast<const ulonglong2*>(wbase + tap * COUT);
                    const ulonglong2 wa = wv[0];
                    const ulonglong2 wb = wv[1];
                    ffma2(acc0[0], fp0, wa.x);
                    ffma2(acc0[1], fp0, wa.y);
                    ffma2(acc0[2], fp0, wb.x);
                    ffma2(acc0[3], fp0, wb.y);
                    ffma2(acc1[0], fp1, wa.x);
                    ffma2(acc1[1], fp1, wa.y);
                    ffma2(acc1[2], fp1, wb.x);
                    ffma2(acc1[3], fp1, wb.y);
                }
            }
        }
    }

    // ---- write out: 2 rows x 8 oc per thread ----
    const int gh0 = th0 + 2 * r2;
    const int gw  = tw0 + cc;
    #pragma unroll
    for (int j = 0; j < 4; ++j) {
        const int oc = ocg * 8 + 2 * j;
        float lo, hi;
        unpack2(acc0[j], lo, hi);
        out[((b * COUT + oc + 0) * HH + gh0) * WW + gw] = lo;
        out[((b * COUT + oc + 1) * HH + gh0) * WW + gw] = hi;
        unpack2(acc1[j], lo, hi);
        out[((b * COUT + oc + 0) * HH + gh0 + 1) * WW + gw] = lo;
        out[((b * COUT + oc + 1) * HH + gh0 + 1) * WW + gw] = hi;
    }
}

extern "C" void kernel_launch(void* const* d_in, const int* in_sizes, int n_in,
                              void* d_out, int out_size) {
    const float* x   = (const float*)d_in[0];
    const float* bw  = (const float*)d_in[1];
    const float* sw  = (const float*)d_in[2];
    const float* ss  = (const float*)d_in[3];
    float* out       = (float*)d_out;

    kan_fuse_kernel<<<(CIN * WCHUNK + 255) / 256, 256>>>(bw, sw, ss);

    dim3 grid(16, BB);   // 16 spatial tiles x 16 batches = 256 CTAs x 512 thr
    kan_conv_kernel<<<grid, THREADS>>>(x, out);
}

// round 8
// speedup vs baseline: 1.3494x; 1.0726x over previous
#include <cuda_runtime.h>

// Problem constants
#define BB   16
#define CIN  8
#define COUT 32
#define HH   64
#define WW   64
#define K2   9
#define NC   8          // spline coefficients per feature
#define NF   9          // features per cin: silu + 8 spline bases
#define TILE 16
#define THREADS 256

#define FR    18                       // halo rows
#define FCR   18                       // real halo cols
#define FCP   20                       // padded col stride (bank-conflict-free)
#define FPIX_S (FR * FCP)              // 360 floats per plane (stored)
#define FPIX_R (FR * FCR)              // 324 real pixels
#define SF_FLOATS (NF * FPIX_S)        // 3240
#define WCHUNK   (NF * K2 * COUT)      // 2592 floats per cin

// Fused weights, computed once per launch by kan_fuse_kernel.
// Layout: gw[c][f][tap][oc], oc fastest.
__device__ float g_fused[CIN * WCHUNK];

__device__ __forceinline__ float silu_f(float x) {
    return x / (1.0f + __expf(-x));
}

// Packed f32x2 FMA: one issue slot, two fp32 FMAs, bit-identical rounding.
__device__ __forceinline__ void ffma2(unsigned long long& d,
                                      unsigned long long a,
                                      unsigned long long b) {
    asm("fma.rn.f32x2 %0, %1, %2, %0;" : "+l"(d) : "l"(a), "l"(b));
}

__device__ __forceinline__ unsigned long long pack2(float v) {
    unsigned long long p;
    asm("mov.b64 %0, {%1, %1};" : "=l"(p) : "f"(v));
    return p;
}

__device__ __forceinline__ void unpack2(unsigned long long p, float& lo, float& hi) {
    asm("mov.b64 {%0, %1}, %2;" : "=f"(lo), "=f"(hi) : "l"(p));
}

// De Boor-Cox recursion, degree 3, uniform knots t[j] = (j-3)*0.4 - 1.0.
// Matches the reference recursion exactly (same formula, fp32).
__device__ __forceinline__ void bspline8(float x, float* __restrict__ out) {
    float t[12];
    #pragma unroll
    for (int j = 0; j < 12; ++j) t[j] = (float)(j - 3) * 0.4f - 1.0f;

    float b[11];
    #pragma unroll
    for (int j = 0; j < 11; ++j)
        b[j] = (x >= t[j] && x < t[j + 1]) ? 1.0f : 0.0f;

    #pragma unroll
    for (int k = 1; k <= 3; ++k) {
        #pragma unroll
        for (int j = 0; j < 10; ++j) {
            if (j < 11 - k) {
                b[j] = (x - t[j]) / (t[j + k] - t[j]) * b[j]
                     + (t[j + k + 1] - x) / (t[j + k + 1] - t[j + 1]) * b[j + 1];
            }
        }
    }
    #pragma unroll
    for (int s = 0; s < NC; ++s) out[s] = b[s];
}

// ---- Kernel A: fuse base/spline weights into g_fused ----
__global__ void kan_fuse_kernel(const float* __restrict__ base_w,
                                const float* __restrict__ spline_w,
                                const float* __restrict__ spline_s)
{
    const int i = blockIdx.x * blockDim.x + threadIdx.x;
    if (i >= CIN * WCHUNK) return;
    const int oc  = i & (COUT - 1);
    const int tap = (i / COUT) % K2;
    const int f   = (i / (COUT * K2)) % NF;
    const int c   = i / WCHUNK;
    const int widx = (oc * CIN + c) * K2 + tap;
    float w;
    if (f == 0) w = base_w[widx];
    else        w = spline_w[widx * NC + (f - 1)] * spline_s[widx];
    g_fused[i] = w;
}

// ---- Kernel B: main conv.
// 256 threads: ocg = tid >> 6 (4 groups of 8 oc); pxg = tid & 63 ->
// 2x2 pixel block: pr = pxg>>3 (rows 2pr,2pr+1), pc = pxg&7 (cols 2pc,2pc+1).
// Warp-uniform ocg -> weight LDS broadcast. Feature planes padded to stride
// 20 floats -> warp feature LDS hit all 32 banks (conflict-free).
// Double-buffered features/weights, ONE barrier per cin.
__global__ void __launch_bounds__(THREADS, 3)
kan_conv_kernel(const float* __restrict__ x,
                float* __restrict__ out)
{
    __shared__ float sF[2][SF_FLOATS];
    __shared__ float sW[2][WCHUNK];

    const int tid  = threadIdx.x;
    const int tile = blockIdx.x;      // 0..15
    const int b    = blockIdx.y;      // 0..15
    const int th0  = (tile >> 2) * TILE;
    const int tw0  = (tile & 3) * TILE;

    const int ocg = tid >> 6;         // 0..3
    const int pxg = tid & 63;
    const int pr  = pxg >> 3;         // 0..7 -> rows 2pr, 2pr+1
    const int pc  = pxg & 7;          // 0..7 -> cols 2pc, 2pc+1

    auto stage_weights = [&](int c, float* dst) {
        const float4* src = reinterpret_cast<const float4*>(g_fused + c * WCHUNK);
        float4* d4 = reinterpret_cast<float4*>(dst);
        #pragma unroll
        for (int k = 0; k < 3; ++k) {
            const int i = tid + k * THREADS;
            if (i < WCHUNK / 4) d4[i] = src[i];
        }
    };
    auto featgen = [&](int c, float* dst) {
        #pragma unroll
        for (int k = 0; k < 2; ++k) {
            const int i = tid + k * THREADS;
            if (i < FPIX_R) {
                const int hc = i % FCR;
                const int hr = i / FCR;
                const int gh = th0 + hr - 1;
                const int gw = tw0 + hc - 1;
                float v = 0.0f;
                if (gh >= 0 && gh < HH && gw >= 0 && gw < WW)
                    v = x[((b * CIN + c) * HH + gh) * WW + gw];
                float bs[NC];
                bspline8(v, bs);
                const int o = hr * FCP + hc;
                dst[o] = silu_f(v);
                #pragma unroll
                for (int s = 0; s < NC; ++s)
                    dst[(s + 1) * FPIX_S + o] = bs[s];
            }
        }
    };

    // Accumulators: 4 px x 8 oc = 32 floats as 16 packed f32x2.
    // acc[px][q]: px = i*2+j (i=row in pair, j=col in pair), q = oc-pair.
    unsigned long long acc[4][4];
    #pragma unroll
    for (int p = 0; p < 4; ++p)
        #pragma unroll
        for (int q = 0; q < 4; ++q) acc[p][q] = 0ULL;

    // ---- prologue: cin 0 into buffer 0 ----
    stage_weights(0, sW[0]);
    featgen(0, sF[0]);

    for (int c = 0; c < CIN; ++c) {
        const int buf = c & 1;
        __syncthreads();   // buf(c) ready; conv(c-1) done with buf^1

        if (c < CIN - 1) {
            stage_weights(c + 1, sW[1 - buf]);
            featgen(c + 1, sF[1 - buf]);
        }

        const float* __restrict__ sFb = sF[buf];
        const float* __restrict__ sWb = sW[buf];

        #pragma unroll 3
        for (int f = 0; f < NF; ++f) {
            // 4x4 feature window, packed to f32x2 once each.
            unsigned long long fp[4][4];
            #pragma unroll
            for (int wr = 0; wr < 4; ++wr)
                #pragma unroll
                for (int wc = 0; wc < 4; ++wc)
                    fp[wr][wc] = pack2(
                        sFb[f * FPIX_S + (2 * pr + wr) * FCP + (2 * pc + wc)]);

            const float* wbase = sWb + (f * K2) * COUT + ocg * 8;

            #pragma unroll
            for (int dh = 0; dh < 3; ++dh) {
                #pragma unroll
                for (int dw = 0; dw < 3; ++dw) {
                    const int tap = dh * 3 + dw;
                    const ulonglong2* wv =
                        reinterpret_cast<const ulonglong2*>(wbase + tap * COUT);
                    const ulonglong2 wa = wv[0];   // oc 0..3 of this group
                    const ulonglong2 wb = wv[1];   // oc 4..7
                    #pragma unroll
                    for (int i = 0; i < 2; ++i) {
                        #pragma unroll
                        for (int j = 0; j < 2; ++j) {
                            const unsigned long long fv = fp[i + dh][j + dw];
                            ffma2(acc[i * 2 + j][0], fv, wa.x);
                            ffma2(acc[i * 2 + j][1], fv, wa.y);
                            ffma2(acc[i * 2 + j][2], fv, wb.x);
                            ffma2(acc[i * 2 + j][3], fv, wb.y);
                        }
                    }
                }
            }
        }
    }

    // ---- write out: 2 rows x 2 cols x 8 oc per thread, float2 over cols ----
    const int gh0 = th0 + 2 * pr;
    const int gw0 = tw0 + 2 * pc;
    #pragma unroll
    for (int i = 0; i < 2; ++i) {
        #pragma unroll
        for (int q = 0; q < 4; ++q) {
            const int oc = ocg * 8 + 2 * q;
            float l0, h0, l1, h1;
            unpack2(acc[i * 2 + 0][q], l0, h0);
            unpack2(acc[i * 2 + 1][q], l1, h1);
            float2* p0 = reinterpret_cast<float2*>(
                &out[((b * COUT + oc + 0) * HH + gh0 + i) * WW + gw0]);
            float2* p1 = reinterpret_cast<float2*>(
                &out[((b * COUT + oc + 1) * HH + gh0 + i) * WW + gw0]);
            *p0 = make_float2(l0, l1);
            *p1 = make_float2(h0, h1);
        }
    }
}

extern "C" void kernel_launch(void* const* d_in, const int* in_sizes, int n_in,
                              void* d_out, int out_size) {
    const float* x   = (const float*)d_in[0];
    const float* bw  = (const float*)d_in[1];
    const float* sw  = (const float*)d_in[2];
    const float* ss  = (const float*)d_in[3];
    float* out       = (float*)d_out;

    kan_fuse_kernel<<<(CIN * WCHUNK + 255) / 256, 256>>>(bw, sw, ss);

    dim3 grid(16, BB);   // 16 spatial tiles x 16 batches = 256 CTAs x 256 thr
    kan_conv_kernel<<<grid, THREADS>>>(x, out);
}

// round 9
// speedup vs baseline: 1.3795x; 1.0223x over previous
#include <cuda_runtime.h>

// Problem constants
#define BB   16
#define CIN  8
#define COUT 32
#define HH   64
#define WW   64
#define K2   9
#define NC   8          // spline coefficients per feature
#define NF   9          // features per cin: silu + 8 spline bases
#define TILE 16
#define THREADS 512

#define FR    18                       // halo rows
#define FCR   18                       // real halo cols
#define FCP   20                       // padded col stride (+1 swizzle slot)
#define FPIX_S (FR * FCP)              // 360 floats per plane (stored)
#define FPIX_R (FR * FCR)              // 324 real pixels
#define SF_FLOATS (NF * FPIX_S)        // 3240
#define WCHUNK   (NF * K2 * COUT)      // 2592 floats per cin

// Row swizzle: +1 for rows whose pair-index is odd -> warp feature LDS hits
// all 32 banks (2x2 px blocking makes all unswizzled offsets even).
#define SWZ(hr) (((hr) >> 1) & 1)

// Fused weights, computed once per launch by kan_fuse_kernel.
// Layout: gw[c][f][tap][oc], oc fastest.
__device__ float g_fused[CIN * WCHUNK];

__device__ __forceinline__ float silu_f(float x) {
    return x / (1.0f + __expf(-x));
}

// Packed f32x2 FMA: one issue slot, two fp32 FMAs, bit-identical rounding.
__device__ __forceinline__ void ffma2(unsigned long long& d,
                                      unsigned long long a,
                                      unsigned long long b) {
    asm("fma.rn.f32x2 %0, %1, %2, %0;" : "+l"(d) : "l"(a), "l"(b));
}

__device__ __forceinline__ unsigned long long pack2(float v) {
    unsigned long long p;
    asm("mov.b64 %0, {%1, %1};" : "=l"(p) : "f"(v));
    return p;
}

__device__ __forceinline__ void unpack2(unsigned long long p, float& lo, float& hi) {
    asm("mov.b64 {%0, %1}, %2;" : "=f"(lo), "=f"(hi) : "l"(p));
}

// De Boor-Cox recursion, degree 3, uniform knots t[j] = (j-3)*0.4 - 1.0.
// Matches the reference recursion exactly (same formula, fp32).
__device__ __forceinline__ void bspline8(float x, float* __restrict__ out) {
    float t[12];
    #pragma unroll
    for (int j = 0; j < 12; ++j) t[j] = (float)(j - 3) * 0.4f - 1.0f;

    float b[11];
    #pragma unroll
    for (int j = 0; j < 11; ++j)
        b[j] = (x >= t[j] && x < t[j + 1]) ? 1.0f : 0.0f;

    #pragma unroll
    for (int k = 1; k <= 3; ++k) {
        #pragma unroll
        for (int j = 0; j < 10; ++j) {
            if (j < 11 - k) {
                b[j] = (x - t[j]) / (t[j + k] - t[j]) * b[j]
                     + (t[j + k + 1] - x) / (t[j + k + 1] - t[j + 1]) * b[j + 1];
            }
        }
    }
    #pragma unroll
    for (int s = 0; s < NC; ++s) out[s] = b[s];
}

// ---- Kernel A: fuse base/spline weights into g_fused ----
__global__ void kan_fuse_kernel(const float* __restrict__ base_w,
                                const float* __restrict__ spline_w,
                                const float* __restrict__ spline_s)
{
    const int i = blockIdx.x * blockDim.x + threadIdx.x;
    if (i >= CIN * WCHUNK) return;
    const int oc  = i & (COUT - 1);
    const int tap = (i / COUT) % K2;
    const int f   = (i / (COUT * K2)) % NF;
    const int c   = i / WCHUNK;
    const int widx = (oc * CIN + c) * K2 + tap;
    float w;
    if (f == 0) w = base_w[widx];
    else        w = spline_w[widx * NC + (f - 1)] * spline_s[widx];
    g_fused[i] = w;
}

// ---- Kernel B: main conv.
// 512 threads: ocg = tid >> 6 (8 groups of 4 oc); pxg = tid & 63 ->
// 2x2 pixel block: pr = pxg>>3 (rows 2pr,2pr+1), pc = pxg&7 (cols 2pc,2pc+1).
// Per tap: 1 broadcast LDS.128 feeds 8 FFMA2 (4 px x 4 oc).
// Rolling 2-row packed window: 16 packs per feature plane.
// Double-buffered features/weights, ONE barrier per cin.
__global__ void __launch_bounds__(THREADS, 2)
kan_conv_kernel(const float* __restrict__ x,
                float* __restrict__ out)
{
    __shared__ float sF[2][SF_FLOATS];
    __shared__ float sW[2][WCHUNK];

    const int tid  = threadIdx.x;
    const int tile = blockIdx.x;      // 0..15
    const int b    = blockIdx.y;      // 0..15
    const int th0  = (tile >> 2) * TILE;
    const int tw0  = (tile & 3) * TILE;

    const int ocg = tid >> 6;         // 0..7 (warp-uniform)
    const int pxg = tid & 63;
    const int pr  = pxg >> 3;         // 0..7 -> rows 2pr, 2pr+1
    const int pc  = pxg & 7;          // 0..7 -> cols 2pc, 2pc+1

    auto stage_weights = [&](int c, float* dst) {
        const float4* src = reinterpret_cast<const float4*>(g_fused + c * WCHUNK);
        float4* d4 = reinterpret_cast<float4*>(dst);
        #pragma unroll
        for (int k = 0; k < 2; ++k) {
            const int i = tid + k * THREADS;
            if (i < WCHUNK / 4) d4[i] = src[i];
        }
    };
    auto featgen = [&](int c, float* dst) {
        if (tid < FPIX_R) {
            const int hc = tid % FCR;
            const int hr = tid / FCR;
            const int gh = th0 + hr - 1;
            const int gw = tw0 + hc - 1;
            float v = 0.0f;
            if (gh >= 0 && gh < HH && gw >= 0 && gw < WW)
                v = x[((b * CIN + c) * HH + gh) * WW + gw];
            float bs[NC];
            bspline8(v, bs);
            const int o = hr * FCP + hc + SWZ(hr);
            dst[o] = silu_f(v);
            #pragma unroll
            for (int s = 0; s < NC; ++s)
                dst[(s + 1) * FPIX_S + o] = bs[s];
        }
    };

    // Accumulators: 4 px x 4 oc = 16 floats as 8 packed f32x2.
    // acc[px][q]: px = i*2+j, q = oc-pair within the 4-oc group.
    unsigned long long acc[4][2];
    #pragma unroll
    for (int p = 0; p < 4; ++p) { acc[p][0] = 0ULL; acc[p][1] = 0ULL; }

    // ---- prologue: cin 0 into buffer 0 ----
    stage_weights(0, sW[0]);
    featgen(0, sF[0]);

    for (int c = 0; c < CIN; ++c) {
        const int buf = c & 1;
        __syncthreads();   // buf(c) ready; conv(c-1) done with buf^1

        if (c < CIN - 1) {
            stage_weights(c + 1, sW[1 - buf]);
            featgen(c + 1, sF[1 - buf]);
        }

        const float* __restrict__ sFb = sF[buf];
        const float* __restrict__ sWb = sW[buf];

        #pragma unroll 3
        for (int f = 0; f < NF; ++f) {
            const float* fpl = sFb + f * FPIX_S;

            // rolling window rows: rw[0] = row (2pr+dh), rw[1] = row (2pr+dh+1)
            unsigned long long rw[2][4];
            #pragma unroll
            for (int k = 0; k < 2; ++k) {
                const int row = 2 * pr + k;
                const int base = row * FCP + 2 * pc + SWZ(row);
                #pragma unroll
                for (int wc = 0; wc < 4; ++wc)
                    rw[k][wc] = pack2(fpl[base + wc]);
            }

            const float* wbase = sWb + (f * K2) * COUT + ocg * 4;

            #pragma unroll
            for (int dh = 0; dh < 3; ++dh) {
                #pragma unroll
                for (int dw = 0; dw < 3; ++dw) {
                    const int tap = dh * 3 + dw;
                    const ulonglong2 w = *reinterpret_cast<const ulonglong2*>(
                        wbase + tap * COUT);
                    #pragma unroll
                    for (int i = 0; i < 2; ++i) {
                        #pragma unroll
                        for (int j = 0; j < 2; ++j) {
                            const unsigned long long fv = rw[i][j + dw];
                            ffma2(acc[i * 2 + j][0], fv, w.x);
                            ffma2(acc[i * 2 + j][1], fv, w.y);
                        }
                    }
                }
                // rotate window: bring in row (2pr + dh + 2)
                if (dh < 2) {
                    #pragma unroll
                    for (int wc = 0; wc < 4; ++wc) rw[0][wc] = rw[1][wc];
                    const int row = 2 * pr + dh + 2;
                    const int base = row * FCP + 2 * pc + SWZ(row);
                    #pragma unroll
                    for (int wc = 0; wc < 4; ++wc)
                        rw[1][wc] = pack2(fpl[base + wc]);
                }
            }
        }
    }

    // ---- write out: 2 rows x 2 cols x 4 oc per thread, float2 over cols ----
    const int gh0 = th0 + 2 * pr;
    const int gw0 = tw0 + 2 * pc;
    #pragma unroll
    for (int i = 0; i < 2; ++i) {
        #pragma unroll
        for (int q = 0; q < 2; ++q) {
            const int oc = ocg * 4 + 2 * q;
            float l0, h0, l1, h1;
            unpack2(acc[i * 2 + 0][q], l0, h0);
            unpack2(acc[i * 2 + 1][q], l1, h1);
            float2* p0 = reinterpret_cast<float2*>(
                &out[((b * COUT + oc + 0) * HH + gh0 + i) * WW + gw0]);
            float2* p1 = reinterpret_cast<float2*>(
                &out[((b * COUT + oc + 1) * HH + gh0 + i) * WW + gw0]);
            *p0 = make_float2(l0, l1);
            *p1 = make_float2(h0, h1);
        }
    }
}

extern "C" void kernel_launch(void* const* d_in, const int* in_sizes, int n_in,
                              void* d_out, int out_size) {
    const float* x   = (const float*)d_in[0];
    const float* bw  = (const float*)d_in[1];
    const float* sw  = (const float*)d_in[2];
    const float* ss  = (const float*)d_in[3];
    float* out       = (float*)d_out;

    kan_fuse_kernel<<<(CIN * WCHUNK + 255) / 256, 256>>>(bw, sw, ss);

    dim3 grid(16, BB);   // 16 spatial tiles x 16 batches = 256 CTAs x 512 thr
    kan_conv_kernel<<<grid, THREADS>>>(x, out);
}